// round 10
// baseline (speedup 1.0000x reference)
#include <cuda_runtime.h>
#include <math.h>
#include <stdint.h>

#define BB 2
#define LL 4096
#define CC 64
#define DI 128
#define SS 16
#define TT 56          // positions per tile
#define NP 58          // TT + 2 halo
#define NTILES 74      // ceil(4096/56)
#define NTH 512
#define GRID (BB*NTILES)   // 148 CTAs = one full wave at 1 CTA/SM

typedef unsigned long long ull;
union F4U2 { float4 f4; ull u2[2]; };

__device__ __forceinline__ ull fma2(ull a, ull b, ull c) {
    ull d; asm("fma.rn.f32x2 %0, %1, %2, %3;" : "=l"(d) : "l"(a), "l"(b), "l"(c));
    return d;
}
__device__ __forceinline__ ull mul2(ull a, ull b) {
    ull d; asm("mul.rn.f32x2 %0, %1, %2;" : "=l"(d) : "l"(a), "l"(b));
    return d;
}
__device__ __forceinline__ ull pack2(float lo, float hi) {
    ull d; asm("mov.b64 %0, {%1, %2};" : "=l"(d) : "f"(lo), "f"(hi));
    return d;
}
__device__ __forceinline__ void unpack2(ull v, float& lo, float& hi) {
    asm("mov.b64 {%0, %1}, %2;" : "=f"(lo), "=f"(hi) : "l"(v));
}

// -------- scratch (device globals; no dynamic allocation allowed) --------
__device__ float g_rgbT[BB*LL*CC];   // [b][l][c]
__device__ float g_dteT[BB*LL*CC];
__device__ float g_buf0[BB*LL*CC];
__device__ float g_buf1[BB*LL*CC];
__device__ float g_hperm[BB*LL*DI*SS];     // permuted h chain [b][l][sg][dd][4]
__device__ float g_hfallback[BB*LL*DI*SS]; // final h if out_size unexpected
__device__ unsigned g_bar;                 // grid-sync arrival counter

__global__ void reset_kernel() { g_bar = 0u; }

__device__ __forceinline__ void grid_sync(unsigned target) {
    __syncthreads();
    if (threadIdx.x == 0) {
        __threadfence();
        atomicAdd(&g_bar, 1u);
        while (atomicAdd(&g_bar, 0u) < target) { }
        __threadfence();
    }
    __syncthreads();
}

// smem layout (floats)
#define OFF_XN      0                       // 58*64  = 3712 (aliased: conv in_s/x_s)
#define OFF_XCRAW   (OFF_XN + NP*64)        // 58*128 = 7424 (aliased: gS, conv wT)
#define OFF_Z       (OFF_XCRAW + NP*128)    // 56*128 = 7168 (aliased: conv_out res)
#define OFF_XC      (OFF_Z + TT*128)        // 56*128 = 7168  (row-major [p][128])
#define OFF_XPT     (OFF_XC + TT*128)       // 8192
#define OFF_DTT     (OFF_XPT + 128*64)      // 4096
#define OFF_OPT     (OFF_DTT + 32*128)      // 8192
#define OFF_DBC     (OFF_OPT + 128*64)      // 56*64 = 3584
#define OFF_CW      (OFF_DBC + TT*64)       // 384
#define OFF_CB      (OFF_CW + 3*128)        // 128
#define OFF_DTB     (OFF_CB + 128)          // 128
#define OFF_DP      (OFF_DTB + 128)         // 128
#define OFF_NW      (OFF_DP + 128)          // 64
#define SMEM_FLOATS (OFF_NW + 64)
#define SMEM_BYTES  (SMEM_FLOATS * 4)       // ~201 KB

__global__ __launch_bounds__(NTH, 1) void fused_kernel(
    const float* __restrict__ rgb, const float* __restrict__ dte,
    const float* __restrict__ w1, const float* __restrict__ b1,
    const float* __restrict__ w2, const float* __restrict__ b2,
    const float* __restrict__ w3, const float* __restrict__ b3,
    const float* __restrict__ normw,
    const float* __restrict__ in_proj_w,
    const float* __restrict__ conv1d_w, const float* __restrict__ conv1d_b,
    const float* __restrict__ x_proj_w,
    const float* __restrict__ dt_proj_w, const float* __restrict__ dt_proj_b,
    const float* __restrict__ A_log, const float* __restrict__ Dp,
    const float* __restrict__ out_proj_w,
    float* out, float* hfinal)
{
    extern __shared__ float sm[];
    float* xn_s    = sm + OFF_XN;
    float* xcraw_s = sm + OFF_XCRAW;
    float* z_s     = sm + OFF_Z;
    float* xc_s    = sm + OFF_XC;     // [p][128] row-major
    float* xprojT  = sm + OFF_XPT;    // [d][j]
    float* dtprojT = sm + OFF_DTT;    // [r][dd]
    float* outprojT= sm + OFF_OPT;    // [dd][c]
    float* dbc_s   = sm + OFF_DBC;    // [pos][64]
    float* cw_s    = sm + OFF_CW;
    float* cb_s    = sm + OFF_CB;
    float* dtb_s   = sm + OFF_DTB;
    float* Dp_s    = sm + OFF_DP;
    float* nw_s    = sm + OFF_NW;
    float* gS      = xcraw_s;         // alias: xcraw dead after phase 2; [p][128]

    const int t    = threadIdx.x;
    const int lane = t & 31;
    const int b    = blockIdx.x / NTILES;
    const int tile = blockIdx.x - b*NTILES;
    const int l0   = tile * TT;

    float* rgbT  = g_rgbT;
    float* dteT  = g_dteT;
    float* buf0  = g_buf0;
    float* buf1  = g_buf1;
    float* hperm = g_hperm;

    // fastA: is exp(A_log[dd][s]) == s+1? (reference builds A = tile(arange(1..16)))
    bool fastA = true;
    {
        const int dd3 = t & 127;
        #pragma unroll
        for (int s = 0; s < SS; s++) {
            float na = __expf(A_log[dd3*16 + s]);
            if (fabsf(na - (float)(s+1)) > 1e-3f) fastA = false;
        }
    }

    // ================= conv_in stage =================
    {
        float* in_s = xn_s;     // [c][TT]
        float* wT   = xcraw_s;  // [c][65]
        for (int which = 0; which < 2; which++) {
            const float* src  = which ? dte : rgb;
            const float* w    = which ? w2 : w1;
            const float* bias = which ? b2 : b1;
            float* dst = which ? dteT : rgbT;
            __syncthreads();
            for (int lin = t; lin < 64*64; lin += NTH)
                wT[(lin & 63)*65 + (lin >> 6)] = w[lin];
            for (int lin = t; lin < 64*TT; lin += NTH) {
                int c = lin / TT, p = lin - c*TT;
                int l = l0 + p;
                in_s[c*TT + p] = (l < LL) ? src[(size_t)(b*64 + c)*LL + l] : 0.0f;
            }
            __syncthreads();
            int o = t & 63, pslot = t >> 6;
            float bv = bias[o];
            for (int p = pslot; p < TT; p += 8) {
                int l = l0 + p;
                if (l >= LL) continue;
                float acc = bv;
                #pragma unroll 8
                for (int c = 0; c < 64; c++)
                    acc += wT[c*65 + o] * in_s[c*TT + p];
                dst[(size_t)(b*LL + l)*64 + o] = acc;
            }
        }
        __syncthreads();
    }

    // ================= stage mamba weights (ONCE) =================
    for (int lin = t; lin < 64*128; lin += NTH) {      // x_proj_w [j][d] -> xprojT[d][j]
        int j = lin >> 7, d = lin & 127;
        xprojT[d*64 + j] = x_proj_w[lin];
    }
    for (int lin = t; lin < 128*32; lin += NTH) {      // dt_proj_w [dd][r] -> dtprojT[r][dd]
        int dd = lin >> 5, r = lin & 31;
        dtprojT[r*128 + dd] = dt_proj_w[lin];
    }
    for (int lin = t; lin < 64*128; lin += NTH) {      // out_proj_w [c][dd] -> outprojT[dd][c]
        int c = lin >> 7, dd = lin & 127;
        outprojT[dd*64 + c] = out_proj_w[lin];
    }
    if (t < 384) { int dd = t / 3, k = t % 3; cw_s[k*128 + dd] = conv1d_w[t]; }
    if (t < 128) { cb_s[t] = conv1d_b[t]; dtb_s[t] = dt_proj_b[t]; Dp_s[t] = Dp[t]; }
    if (t < 64)  { nw_s[t] = normw[t]; }

    unsigned ep = 1;
    grid_sync(GRID*ep); ep++;

    // ================= 6 fused residual mamba blocks =================
    const int row = t & 255;
    for (int blk = 0; blk < 6; blk++) {
        const float* base = (blk & 1) ? dteT : rgbT;
        const float* prev = (blk == 0) ? (const float*)0
                                       : ((blk & 1) ? buf0 : buf1);
        float* outp = (blk & 1) ? buf1 : buf0;
        const int hmode = (blk == 0) ? 0 : (blk == 5 ? 2 : 1);

        // ---- phase 1a: x_in = base (+prev), rmsnorm -> xn_s ----
        {
            int w = t >> 5;
            for (int hp = w; hp < NP; hp += 16) {
                int l = l0 - 1 + hp;
                if (l < 0 || l >= LL) continue;
                size_t off = ((size_t)(b*LL + l)) * 64;
                float v0 = base[off + lane];
                float v1 = base[off + 32 + lane];
                if (prev) { v0 += prev[off + lane]; v1 += prev[off + 32 + lane]; }
                float ssum = v0*v0 + v1*v1;
                #pragma unroll
                for (int m = 16; m > 0; m >>= 1) ssum += __shfl_xor_sync(0xffffffffu, ssum, m);
                float rs = rsqrtf(ssum * (1.0f/64.0f) + 1e-5f);
                xn_s[hp*64 + lane]      = v0 * rs * nw_s[lane];
                xn_s[hp*64 + 32 + lane] = v1 * rs * nw_s[32 + lane];
            }
        }
        __syncthreads();

        // ---- phase 1b: in_proj (weights in regs; acts distributed + shuffled) ----
        {
            ull w2r[32];   // pair j = (w[row][2j], w[row][2j+1])
            {
                const float4* wp = (const float4*)(in_proj_w + row*64);
                #pragma unroll
                for (int k = 0; k < 16; k++) {
                    F4U2 c; c.f4 = wp[k];
                    w2r[2*k]   = c.u2[0];
                    w2r[2*k+1] = c.u2[1];
                }
            }
            int ps = t >> 8;
            for (int hp = ps; hp < NP; hp += 2) {
                int l = l0 - 1 + hp;
                if (l < 0 || l >= LL) {
                    if (row < 128) xcraw_s[hp*128 + row] = 0.0f;
                    continue;
                }
                // distinct-lane act load: lane ℓ holds xn[hp][2ℓ], xn[hp][2ℓ+1]
                float2 myact = *(const float2*)(xn_s + hp*64 + lane*2);
                ull acc2 = pack2(0.0f, 0.0f);
                #pragma unroll
                for (int s = 0; s < 32; s++) {
                    float a0 = __shfl_sync(0xffffffffu, myact.x, s);
                    float a1 = __shfl_sync(0xffffffffu, myact.y, s);
                    acc2 = fma2(w2r[s], pack2(a0, a1), acc2);
                }
                float alo, ahi; unpack2(acc2, alo, ahi);
                float acc = alo + ahi;
                if (row < 128) xcraw_s[hp*128 + row] = acc;
                else if (hp >= 1 && hp <= TT) z_s[(hp-1)*128 + (row-128)] = acc;
            }
        }
        __syncthreads();

        // ---- phase 2: depthwise conv1d (k=3, same) + silu -> xc_s [p][128] ----
        for (int idx = t; idx < TT*128; idx += NTH) {
            int po = idx >> 7, dd = idx & 127;
            int hp = po + 1;
            float v = cw_s[dd]         * xcraw_s[(hp-1)*128 + dd]
                    + cw_s[128 + dd]   * xcraw_s[hp*128 + dd]
                    + cw_s[256 + dd]   * xcraw_s[(hp+1)*128 + dd]
                    + cb_s[dd];
            xc_s[po*128 + dd] = v / (1.0f + __expf(-v));
        }
        __syncthreads();

        // ---- phase 3a: x_proj -> dbc_s[p][64]  (acts staged distinct-lane + shfl) ----
        {
            int jt = t & 15;
            int pt = t >> 4;
            if (pt < TT/2) {
                const int p0 = pt*2, p1 = p0 + 1;
                // lane slices: half-warp h = lane&16 covers its own (p0,p1)
                const int sl = lane & 15;
                float4 A0 = *(const float4*)(xc_s + p0*128 + sl*4);
                float4 A1 = *(const float4*)(xc_s + p0*128 + 64 + sl*4);
                float4 B0 = *(const float4*)(xc_s + p1*128 + sl*4);
                float4 B1 = *(const float4*)(xc_s + p1*128 + 64 + sl*4);
                ull a0l = pack2(0,0), a0h = pack2(0,0);
                ull a1l = pack2(0,0), a1h = pack2(0,0);
                #pragma unroll
                for (int d4 = 0; d4 < 32; d4++) {
                    int srcl = (lane & 16) | (d4 & 15);
                    float4 sa = (d4 < 16) ? A0 : A1;
                    float4 sb = (d4 < 16) ? B0 : B1;
                    float xa[4], xb[4];
                    xa[0] = __shfl_sync(0xffffffffu, sa.x, srcl);
                    xa[1] = __shfl_sync(0xffffffffu, sa.y, srcl);
                    xa[2] = __shfl_sync(0xffffffffu, sa.z, srcl);
                    xa[3] = __shfl_sync(0xffffffffu, sa.w, srcl);
                    xb[0] = __shfl_sync(0xffffffffu, sb.x, srcl);
                    xb[1] = __shfl_sync(0xffffffffu, sb.y, srcl);
                    xb[2] = __shfl_sync(0xffffffffu, sb.z, srcl);
                    xb[3] = __shfl_sync(0xffffffffu, sb.w, srcl);
                    #pragma unroll
                    for (int e = 0; e < 4; e++) {
                        F4U2 w; w.f4 = *(const float4*)(xprojT + (d4*4+e)*64 + jt*4);
                        ull xa2 = pack2(xa[e], xa[e]);
                        ull xb2 = pack2(xb[e], xb[e]);
                        a0l = fma2(w.u2[0], xa2, a0l);
                        a0h = fma2(w.u2[1], xa2, a0h);
                        a1l = fma2(w.u2[0], xb2, a1l);
                        a1h = fma2(w.u2[1], xb2, a1h);
                    }
                }
                F4U2 o0; o0.u2[0] = a0l; o0.u2[1] = a0h;
                F4U2 o1; o1.u2[0] = a1l; o1.u2[1] = a1h;
                ((float4*)(dbc_s + p0*64))[jt] = o0.f4;
                ((float4*)(dbc_s + p1*64))[jt] = o1.f4;
            }
        }
        __syncthreads();

        // ---- phase 3bc: dt_proj, softplus, SSM (exp-chain), gating -> gS ----
        // dbc row distributed across lanes + shuffled (no broadcast LDS).
        {
            const int dd3 = t & 127;
            const int ps4 = t >> 7;
            ull wdt2[16];
            #pragma unroll
            for (int r = 0; r < 16; r++)
                wdt2[r] = pack2(dtprojT[(2*r)*128 + dd3], dtprojT[(2*r+1)*128 + dd3]);
            const float dtbv = dtb_s[dd3];
            const float Dpv  = Dp_s[dd3];
            float4* HS = (float4*)hperm;
            float4* HD = (float4*)hfinal;
            for (int chunk = 0; chunk < TT/4; chunk++) {
                int po = (chunk << 2) | ps4;
                int l  = l0 + po;
                const bool lvalid = (l < LL);     // warp-uniform
                // distinct-lane loads of this position's dbc row
                float dval  = dbc_s[po*64 + lane];        // delta_raw[lane]
                float bcval = dbc_s[po*64 + 32 + lane];   // B[lane<16] / C[lane-16]
                // dt_proj dot via shuffles (weights stationary)
                ull dr2 = pack2(dtbv, 0.0f);
                #pragma unroll
                for (int k = 0; k < 16; k++) {
                    float s0 = __shfl_sync(0xffffffffu, dval, 2*k);
                    float s1 = __shfl_sync(0xffffffffu, dval, 2*k+1);
                    dr2 = fma2(wdt2[k], pack2(s0, s1), dr2);
                }
                float alo, ahi; unpack2(dr2, alo, ahi);
                float dr = alo + ahi;
                float delta = (dr > 20.0f) ? dr : log1pf(__expf(dr));
                float xcv = xc_s[po*128 + dd3];
                float dBx = delta * xcv;
                ull dBx2 = pack2(dBx, dBx);
                ull B2[8], C2[8];
                #pragma unroll
                for (int k = 0; k < 8; k++) {
                    float b0 = __shfl_sync(0xffffffffu, bcval, 2*k);
                    float b1 = __shfl_sync(0xffffffffu, bcval, 2*k+1);
                    B2[k] = pack2(b0, b1);
                }
                #pragma unroll
                for (int k = 0; k < 8; k++) {
                    float c0 = __shfl_sync(0xffffffffu, bcval, 16 + 2*k);
                    float c1 = __shfl_sync(0xffffffffu, bcval, 17 + 2*k);
                    C2[k] = pack2(c0, c1);
                }
                size_t pos512 = ((size_t)(b*LL + (lvalid ? l : 0))) << 9;
                ull hv2[8];
                if (hmode == 0) {
                    #pragma unroll
                    for (int k = 0; k < 8; k++) hv2[k] = pack2(0.0f, 0.0f);
                } else {
                    #pragma unroll
                    for (int sg = 0; sg < 4; sg++) {
                        F4U2 v;
                        v.f4 = lvalid ? HS[pos512 + (sg<<7) + dd3]
                                      : make_float4(0.f,0.f,0.f,0.f);
                        hv2[2*sg] = v.u2[0]; hv2[2*sg+1] = v.u2[1];
                    }
                }
                ull y2 = pack2(0.0f, 0.0f);
                if (fastA) {
                    float E1 = __expf(-delta);
                    float Esq = E1*E1;
                    ull Echain = pack2(Esq, Esq);
                    ull da = pack2(E1, Esq);
                    #pragma unroll
                    for (int k = 0; k < 8; k++) {
                        ull tmp = mul2(dBx2, B2[k]);
                        ull hn  = fma2(da, hv2[k], tmp);
                        hv2[k] = hn;
                        y2 = fma2(hn, C2[k], y2);
                        if (k < 7) da = mul2(da, Echain);
                    }
                } else {
                    #pragma unroll
                    for (int k = 0; k < 8; k++) {
                        float na0 = __expf(__ldg(&A_log[dd3*16 + 2*k]));
                        float na1 = __expf(__ldg(&A_log[dd3*16 + 2*k + 1]));
                        ull da = pack2(__expf(-delta*na0), __expf(-delta*na1));
                        ull tmp = mul2(dBx2, B2[k]);
                        ull hn  = fma2(da, hv2[k], tmp);
                        hv2[k] = hn;
                        y2 = fma2(hn, C2[k], y2);
                    }
                }
                float ylo, yhi; unpack2(y2, ylo, yhi);
                float y = ylo + yhi;
                if (lvalid) {
                    if (hmode == 2) {
                        #pragma unroll
                        for (int sg = 0; sg < 4; sg++) {
                            F4U2 v; v.u2[0] = hv2[2*sg]; v.u2[1] = hv2[2*sg+1];
                            HD[pos512 + (dd3<<2) + sg] = v.f4;
                        }
                    } else {
                        #pragma unroll
                        for (int sg = 0; sg < 4; sg++) {
                            F4U2 v; v.u2[0] = hv2[2*sg]; v.u2[1] = hv2[2*sg+1];
                            HS[pos512 + (sg<<7) + dd3] = v.f4;
                        }
                    }
                }
                y += Dpv * xcv;
                float zv = z_s[po*128 + dd3];
                gS[po*128 + dd3] = y * (zv / (1.0f + __expf(-zv)));
            }
        }
        __syncthreads();

        // ---- phase 3d: out_proj + residual (acts staged distinct-lane + shfl) ----
        {
            int jt = t & 15;
            int pt = t >> 4;
            if (pt < TT/2) {
                const int p0 = pt*2, p1 = p0 + 1;
                const int sl = lane & 15;
                float4 A0 = *(const float4*)(gS + p0*128 + sl*4);
                float4 A1 = *(const float4*)(gS + p0*128 + 64 + sl*4);
                float4 B0 = *(const float4*)(gS + p1*128 + sl*4);
                float4 B1 = *(const float4*)(gS + p1*128 + 64 + sl*4);
                ull a0l = pack2(0,0), a0h = pack2(0,0);
                ull a1l = pack2(0,0), a1h = pack2(0,0);
                #pragma unroll
                for (int d4 = 0; d4 < 32; d4++) {
                    int srcl = (lane & 16) | (d4 & 15);
                    float4 sa = (d4 < 16) ? A0 : A1;
                    float4 sb = (d4 < 16) ? B0 : B1;
                    float ga[4], gb[4];
                    ga[0] = __shfl_sync(0xffffffffu, sa.x, srcl);
                    ga[1] = __shfl_sync(0xffffffffu, sa.y, srcl);
                    ga[2] = __shfl_sync(0xffffffffu, sa.z, srcl);
                    ga[3] = __shfl_sync(0xffffffffu, sa.w, srcl);
                    gb[0] = __shfl_sync(0xffffffffu, sb.x, srcl);
                    gb[1] = __shfl_sync(0xffffffffu, sb.y, srcl);
                    gb[2] = __shfl_sync(0xffffffffu, sb.z, srcl);
                    gb[3] = __shfl_sync(0xffffffffu, sb.w, srcl);
                    #pragma unroll
                    for (int e = 0; e < 4; e++) {
                        F4U2 w; w.f4 = *(const float4*)(outprojT + (d4*4+e)*64 + jt*4);
                        ull ga2 = pack2(ga[e], ga[e]);
                        ull gb2 = pack2(gb[e], gb[e]);
                        a0l = fma2(w.u2[0], ga2, a0l);
                        a0h = fma2(w.u2[1], ga2, a0h);
                        a1l = fma2(w.u2[0], gb2, a1l);
                        a1h = fma2(w.u2[1], gb2, a1h);
                    }
                }
                F4U2 o0; o0.u2[0] = a0l; o0.u2[1] = a0h;
                F4U2 o1; o1.u2[0] = a1l; o1.u2[1] = a1h;
                if (l0 + p0 < LL) {
                    float4 r0 = ((const float4*)(xn_s + (p0+1)*64))[jt];
                    o0.f4.x += r0.x; o0.f4.y += r0.y; o0.f4.z += r0.z; o0.f4.w += r0.w;
                    ((float4*)(outp + ((size_t)(b*LL + l0 + p0))*64))[jt] = o0.f4;
                }
                if (l0 + p1 < LL) {
                    float4 r1 = ((const float4*)(xn_s + (p1+1)*64))[jt];
                    o1.f4.x += r1.x; o1.f4.y += r1.y; o1.f4.z += r1.z; o1.f4.w += r1.w;
                    ((float4*)(outp + ((size_t)(b*LL + l0 + p1))*64))[jt] = o1.f4;
                }
            }
        }

        if (blk < 5) { grid_sync(GRID*ep); ep++; }
    }

    // ================= conv_out stage (pointwise in l: no grid sync needed) =======
    __syncthreads();
    {
        float* x_s = xn_s;     // [p][65]
        float* wT3 = xcraw_s;  // [c][65]
        float* res = z_s;      // [o][57]
        const float* fin = buf1;   // block 5 wrote buf1
        for (int lin = t; lin < 64*64; lin += NTH)
            wT3[(lin & 63)*65 + (lin >> 6)] = w3[lin];
        for (int lin = t; lin < TT*64; lin += NTH) {
            int p = lin >> 6, c = lin & 63;
            int l = l0 + p;
            x_s[p*65 + c] = (l < LL) ? fin[(size_t)(b*LL + l)*64 + c] : 0.0f;
        }
        __syncthreads();
        int o = t & 63, pslot = t >> 6;
        float bv = b3[o];
        for (int p = pslot; p < TT; p += 8) {
            float acc = bv;
            #pragma unroll 8
            for (int c = 0; c < 64; c++)
                acc += wT3[c*65 + o] * x_s[p*65 + c];
            res[o*57 + p] = acc;
        }
        __syncthreads();
        for (int lin = t; lin < 64*TT; lin += NTH) {
            int oo = lin / TT, p = lin - oo*TT;
            int l = l0 + p;
            if (l < LL) out[(size_t)(b*64 + oo)*LL + l] = res[oo*57 + p];
        }
    }
}

// ---------------- launch ----------------
extern "C" void kernel_launch(void* const* d_in, const int* in_sizes, int n_in,
                              void* d_out, int out_size) {
    const float* rgb   = (const float*)d_in[0];
    const float* dte   = (const float*)d_in[1];
    const float* w1    = (const float*)d_in[2];
    const float* b1    = (const float*)d_in[3];
    const float* w2    = (const float*)d_in[4];
    const float* b2    = (const float*)d_in[5];
    const float* w3    = (const float*)d_in[6];
    const float* b3    = (const float*)d_in[7];
    const float* normw = (const float*)d_in[8];
    const float* inpw  = (const float*)d_in[9];
    const float* c1w   = (const float*)d_in[10];
    const float* c1b   = (const float*)d_in[11];
    const float* xpw   = (const float*)d_in[12];
    const float* dtw   = (const float*)d_in[13];
    const float* dtb   = (const float*)d_in[14];
    const float* alog  = (const float*)d_in[15];
    const float* DpP   = (const float*)d_in[16];
    const float* opw   = (const float*)d_in[17];

    float* out = (float*)d_out;
    const int convN = BB*CC*LL;                  // 524288
    const long long hN = (long long)BB*LL*DI*SS; // 16777216
    float* hfinal;
    if (out_size >= convN + hN) {
        hfinal = out + convN;
    } else {
        void* p; cudaGetSymbolAddress(&p, g_hfallback); hfinal = (float*)p;
    }

    cudaFuncSetAttribute(fused_kernel,
                         cudaFuncAttributeMaxDynamicSharedMemorySize, SMEM_BYTES);

    reset_kernel<<<1, 1>>>();
    fused_kernel<<<GRID, NTH, SMEM_BYTES>>>(
        rgb, dte, w1, b1, w2, b2, w3, b3,
        normw, inpw, c1w, c1b, xpw, dtw, dtb, alog, DpP, opw,
        out, hfinal);
    (void)in_sizes; (void)n_in;
}

// round 11
// speedup vs baseline: 1.3580x; 1.3580x over previous
#include <cuda_runtime.h>
#include <math.h>
#include <stdint.h>

#define BB 2
#define LL 4096
#define CC 64
#define DI 128
#define SS 16
#define TT 56          // positions per tile
#define NP 58          // TT + 2 halo
#define NPX 60         // xnT stride (16B-aligned rows)
#define NTILES 74      // ceil(4096/56)
#define NTH 512
#define GRID (BB*NTILES)   // 148 CTAs = one full wave at 1 CTA/SM

typedef unsigned long long ull;
union F4U2 { float4 f4; ull u2[2]; };

__device__ __forceinline__ ull fma2(ull a, ull b, ull c) {
    ull d; asm("fma.rn.f32x2 %0, %1, %2, %3;" : "=l"(d) : "l"(a), "l"(b), "l"(c));
    return d;
}
__device__ __forceinline__ ull mul2(ull a, ull b) {
    ull d; asm("mul.rn.f32x2 %0, %1, %2;" : "=l"(d) : "l"(a), "l"(b));
    return d;
}
__device__ __forceinline__ ull pack2(float lo, float hi) {
    ull d; asm("mov.b64 %0, {%1, %2};" : "=l"(d) : "f"(lo), "f"(hi));
    return d;
}
__device__ __forceinline__ void unpack2(ull v, float& lo, float& hi) {
    asm("mov.b64 {%0, %1}, %2;" : "=f"(lo), "=f"(hi) : "l"(v));
}

// -------- scratch (device globals; no dynamic allocation allowed) --------
__device__ float g_rgbT[BB*LL*CC];   // [b][l][c]
__device__ float g_dteT[BB*LL*CC];
__device__ float g_buf0[BB*LL*CC];
__device__ float g_buf1[BB*LL*CC];
__device__ float g_wT[64*256];             // in_proj transposed [d][row]
__device__ float g_hperm[BB*LL*DI*SS];     // permuted h chain [b][l][sg][dd][4]
__device__ float g_hfallback[BB*LL*DI*SS]; // final h if out_size unexpected
__device__ unsigned g_bar;                 // grid-sync arrival counter

__global__ void reset_kernel() { g_bar = 0u; }

__device__ __forceinline__ void grid_sync(unsigned target) {
    __syncthreads();
    if (threadIdx.x == 0) {
        __threadfence();
        atomicAdd(&g_bar, 1u);
        while (atomicAdd(&g_bar, 0u) < target) { }
        __threadfence();
    }
    __syncthreads();
}

// smem layout (floats)
#define OFF_XN      0                       // xnT [c][NPX] = 64*60 = 3840 (alias conv bufs)
#define OFF_XNR     (OFF_XN + 64*NPX)       // xn_r [p][64] = 3584
#define OFF_XCRAW   (OFF_XNR + TT*64)       // 58*128 = 7424 (alias gS, conv wT)
#define OFF_Z       (OFF_XCRAW + NP*128)    // 7168 (alias conv_out res)
#define OFF_XC      (OFF_Z + TT*128)        // 7168  [p][128]
#define OFF_XPT     (OFF_XC + TT*128)       // 8192
#define OFF_DTT     (OFF_XPT + 128*64)      // 4096
#define OFF_OPT     (OFF_DTT + 32*128)      // 8192
#define OFF_DBC     (OFF_OPT + 128*64)      // 3584
#define OFF_CW      (OFF_DBC + TT*64)       // 384
#define OFF_CB      (OFF_CW + 3*128)        // 128
#define OFF_DTB     (OFF_CB + 128)          // 128
#define OFF_DP      (OFF_DTB + 128)         // 128
#define OFF_NW      (OFF_DP + 128)          // 64
#define SMEM_FLOATS (OFF_NW + 64)
#define SMEM_BYTES  (SMEM_FLOATS * 4)       // ~216 KB

__global__ __launch_bounds__(NTH, 1) void fused_kernel(
    const float* __restrict__ rgb, const float* __restrict__ dte,
    const float* __restrict__ w1, const float* __restrict__ b1,
    const float* __restrict__ w2, const float* __restrict__ b2,
    const float* __restrict__ w3, const float* __restrict__ b3,
    const float* __restrict__ normw,
    const float* __restrict__ in_proj_w,
    const float* __restrict__ conv1d_w, const float* __restrict__ conv1d_b,
    const float* __restrict__ x_proj_w,
    const float* __restrict__ dt_proj_w, const float* __restrict__ dt_proj_b,
    const float* __restrict__ A_log, const float* __restrict__ Dp,
    const float* __restrict__ out_proj_w,
    float* out, float* hfinal)
{
    extern __shared__ float sm[];
    float* xn_s    = sm + OFF_XN;     // xnT [c][NPX]
    float* xn_r    = sm + OFF_XNR;    // [p][64] for residual
    float* xcraw_s = sm + OFF_XCRAW;
    float* z_s     = sm + OFF_Z;
    float* xc_s    = sm + OFF_XC;     // [p][128]
    float* xprojT  = sm + OFF_XPT;    // [d][j]
    float* dtprojT = sm + OFF_DTT;    // [r][dd]
    float* outprojT= sm + OFF_OPT;    // [dd][c]
    float* dbc_s   = sm + OFF_DBC;    // [pos][64]
    float* cw_s    = sm + OFF_CW;
    float* cb_s    = sm + OFF_CB;
    float* dtb_s   = sm + OFF_DTB;
    float* Dp_s    = sm + OFF_DP;
    float* nw_s    = sm + OFF_NW;
    float* gS      = xcraw_s;         // alias: xcraw dead after phase 2; [p][128]

    const int t    = threadIdx.x;
    const int lane = t & 31;
    const int b    = blockIdx.x / NTILES;
    const int tile = blockIdx.x - b*NTILES;
    const int l0   = tile * TT;

    float* rgbT  = g_rgbT;
    float* dteT  = g_dteT;
    float* buf0  = g_buf0;
    float* buf1  = g_buf1;
    float* hperm = g_hperm;

    // fastA: is exp(A_log[dd][s]) == s+1? (reference builds A = tile(arange(1..16)))
    bool fastA = true;
    {
        const int dd3 = t & 127;
        #pragma unroll
        for (int s = 0; s < SS; s++) {
            float na = __expf(A_log[dd3*16 + s]);
            if (fabsf(na - (float)(s+1)) > 1e-3f) fastA = false;
        }
    }

    // ================= conv_in stage =================
    {
        float* in_s = xn_s;     // [c][TT] 3584 <= 3840
        float* wT   = xcraw_s;  // [c][65]
        for (int which = 0; which < 2; which++) {
            const float* src  = which ? dte : rgb;
            const float* w    = which ? w2 : w1;
            const float* bias = which ? b2 : b1;
            float* dst = which ? dteT : rgbT;
            __syncthreads();
            for (int lin = t; lin < 64*64; lin += NTH)
                wT[(lin & 63)*65 + (lin >> 6)] = w[lin];
            for (int lin = t; lin < 64*TT; lin += NTH) {
                int c = lin / TT, p = lin - c*TT;
                int l = l0 + p;
                in_s[c*TT + p] = (l < LL) ? src[(size_t)(b*64 + c)*LL + l] : 0.0f;
            }
            __syncthreads();
            int o = t & 63, pslot = t >> 6;
            float bv = bias[o];
            for (int p = pslot; p < TT; p += 8) {
                int l = l0 + p;
                if (l >= LL) continue;
                float acc = bv;
                #pragma unroll 8
                for (int c = 0; c < 64; c++)
                    acc += wT[c*65 + o] * in_s[c*TT + p];
                dst[(size_t)(b*LL + l)*64 + o] = acc;
            }
        }
        __syncthreads();
    }

    // CTA 0 builds the transposed in_proj copy (visible to all after grid_sync)
    if (blockIdx.x == 0) {
        for (int lin = t; lin < 64*256; lin += NTH) {
            int d = lin >> 8, r = lin & 255;
            g_wT[d*256 + r] = in_proj_w[r*64 + d];
        }
    }

    // ================= stage mamba weights (ONCE) =================
    for (int lin = t; lin < 64*128; lin += NTH) {      // x_proj_w [j][d] -> xprojT[d][j]
        int j = lin >> 7, d = lin & 127;
        xprojT[d*64 + j] = x_proj_w[lin];
    }
    for (int lin = t; lin < 128*32; lin += NTH) {      // dt_proj_w [dd][r] -> dtprojT[r][dd]
        int dd = lin >> 5, r = lin & 31;
        dtprojT[r*128 + dd] = dt_proj_w[lin];
    }
    for (int lin = t; lin < 64*128; lin += NTH) {      // out_proj_w [c][dd] -> outprojT[dd][c]
        int c = lin >> 7, dd = lin & 127;
        outprojT[dd*64 + c] = out_proj_w[lin];
    }
    if (t < 384) { int dd = t / 3, k = t % 3; cw_s[k*128 + dd] = conv1d_w[t]; }
    if (t < 128) { cb_s[t] = conv1d_b[t]; dtb_s[t] = dt_proj_b[t]; Dp_s[t] = Dp[t]; }
    if (t < 64)  { nw_s[t] = normw[t]; }

    unsigned ep = 1;
    grid_sync(GRID*ep); ep++;

    // ================= 6 fused residual mamba blocks =================
    for (int blk = 0; blk < 6; blk++) {
        const float* base = (blk & 1) ? dteT : rgbT;
        const float* prev = (blk == 0) ? (const float*)0
                                       : ((blk & 1) ? buf0 : buf1);
        float* outp = (blk & 1) ? buf1 : buf0;
        const int hmode = (blk == 0) ? 0 : (blk == 5 ? 2 : 1);

        // ---- phase 1a: x_in = base (+prev), rmsnorm -> xnT (+xn_r copy) ----
        {
            int w = t >> 5;
            for (int hp = w; hp < NP; hp += 16) {
                int l = l0 - 1 + hp;       // warp-uniform
                float o0 = 0.0f, o1 = 0.0f;
                if (l >= 0 && l < LL) {
                    size_t off = ((size_t)(b*LL + l)) * 64;
                    float v0 = base[off + lane];
                    float v1 = base[off + 32 + lane];
                    if (prev) { v0 += prev[off + lane]; v1 += prev[off + 32 + lane]; }
                    float ssum = v0*v0 + v1*v1;
                    #pragma unroll
                    for (int m = 16; m > 0; m >>= 1)
                        ssum += __shfl_xor_sync(0xffffffffu, ssum, m);
                    float rs = rsqrtf(ssum * (1.0f/64.0f) + 1e-5f);
                    o0 = v0 * rs * nw_s[lane];
                    o1 = v1 * rs * nw_s[32 + lane];
                }
                xn_s[lane*NPX + hp]        = o0;
                xn_s[(32 + lane)*NPX + hp] = o1;
                if (hp >= 1 && hp <= TT) {
                    xn_r[(hp-1)*64 + lane]      = o0;
                    xn_r[(hp-1)*64 + 32 + lane] = o1;
                }
            }
        }
        __syncthreads();

        // ---- phase 1b: in_proj as register-tiled GEMM (4 rows x 8 hp / thread) ----
        // weights stream distinct-lane from g_wT (L2); acts broadcast from xnT
        {
            const int rg  = t & 63;        // rowgroup: rows 4rg..4rg+3
            const int hpb = (t >> 6) << 3; // hp base: 8 hp per thread
            ull accl[8], acch[8];
            #pragma unroll
            for (int i = 0; i < 8; i++) { accl[i] = pack2(0,0); acch[i] = pack2(0,0); }
            const float4* wp = (const float4*)g_wT;   // [d][64 float4s]
            #pragma unroll 4
            for (int d = 0; d < 64; d++) {
                F4U2 w; w.f4 = __ldg(&wp[d*64 + rg]);
                const float4* xp = (const float4*)(xn_s + d*NPX + hpb); // aligned
                float4 xa = xp[0], xb = xp[1];
                float xs[8] = {xa.x, xa.y, xa.z, xa.w, xb.x, xb.y, xb.z, xb.w};
                #pragma unroll
                for (int i = 0; i < 8; i++) {
                    ull xd = pack2(xs[i], xs[i]);
                    accl[i] = fma2(w.u2[0], xd, accl[i]);
                    acch[i] = fma2(w.u2[1], xd, acch[i]);
                }
            }
            #pragma unroll
            for (int i = 0; i < 8; i++) {
                int hp = hpb + i;
                if (hp >= NP) break;
                F4U2 v; v.u2[0] = accl[i]; v.u2[1] = acch[i];
                if (rg < 32) {
                    *(float4*)(xcraw_s + hp*128 + rg*4) = v.f4;   // xc rows 0..127
                } else if (hp >= 1 && hp <= TT) {
                    *(float4*)(z_s + (hp-1)*128 + (rg-32)*4) = v.f4; // z rows 128..255
                }
            }
        }
        __syncthreads();

        // ---- phase 2: depthwise conv1d (k=3, same) + silu -> xc_s [p][128] ----
        for (int idx = t; idx < TT*128; idx += NTH) {
            int po = idx >> 7, dd = idx & 127;
            int hp = po + 1;
            float v = cw_s[dd]         * xcraw_s[(hp-1)*128 + dd]
                    + cw_s[128 + dd]   * xcraw_s[hp*128 + dd]
                    + cw_s[256 + dd]   * xcraw_s[(hp+1)*128 + dd]
                    + cb_s[dd];
            xc_s[po*128 + dd] = v / (1.0f + __expf(-v));
        }
        __syncthreads();

        // ---- phase 3a: x_proj -> dbc_s[p][64]  (4j x 2p tiles, f32x2, 4d unroll) ----
        {
            int jt = t & 15;
            int pt = t >> 4;
            if (pt < TT/2) {
                const int p0 = pt*2, p1 = p0 + 1;
                ull a0l = pack2(0,0), a0h = pack2(0,0);
                ull a1l = pack2(0,0), a1h = pack2(0,0);
                #pragma unroll 4
                for (int d4 = 0; d4 < 32; d4++) {
                    float4 xa4 = *(const float4*)(xc_s + p0*128 + d4*4);
                    float4 xb4 = *(const float4*)(xc_s + p1*128 + d4*4);
                    float xa[4] = {xa4.x, xa4.y, xa4.z, xa4.w};
                    float xb[4] = {xb4.x, xb4.y, xb4.z, xb4.w};
                    #pragma unroll
                    for (int e = 0; e < 4; e++) {
                        F4U2 w; w.f4 = *(const float4*)(xprojT + (d4*4+e)*64 + jt*4);
                        ull xa2 = pack2(xa[e], xa[e]);
                        ull xb2 = pack2(xb[e], xb[e]);
                        a0l = fma2(w.u2[0], xa2, a0l);
                        a0h = fma2(w.u2[1], xa2, a0h);
                        a1l = fma2(w.u2[0], xb2, a1l);
                        a1h = fma2(w.u2[1], xb2, a1h);
                    }
                }
                F4U2 o0; o0.u2[0] = a0l; o0.u2[1] = a0h;
                F4U2 o1; o1.u2[0] = a1l; o1.u2[1] = a1h;
                ((float4*)(dbc_s + p0*64))[jt] = o0.f4;
                ((float4*)(dbc_s + p1*64))[jt] = o1.f4;
            }
        }
        __syncthreads();

        // ---- phase 3bc: dt_proj (f32x2), softplus, SSM (exp-chain), gating -> gS ----
        {
            const int dd3 = t & 127;
            const int ps4 = t >> 7;
            ull wdt2[16];
            #pragma unroll
            for (int r = 0; r < 16; r++)
                wdt2[r] = pack2(dtprojT[(2*r)*128 + dd3], dtprojT[(2*r+1)*128 + dd3]);
            const float dtbv = dtb_s[dd3];
            const float Dpv  = Dp_s[dd3];
            float4* HS = (float4*)hperm;
            float4* HD = (float4*)hfinal;
            for (int chunk = 0; chunk < TT/4; chunk++) {
                int po = (chunk << 2) | ps4;
                int l  = l0 + po;
                const bool lvalid = (l < LL);     // warp-uniform
                const float4* db4 = (const float4*)(dbc_s + po*64);
                ull acc2 = pack2(dtbv, 0.0f);
                #pragma unroll
                for (int k = 0; k < 8; k++) {
                    F4U2 v; v.f4 = db4[k];
                    acc2 = fma2(wdt2[2*k],   v.u2[0], acc2);
                    acc2 = fma2(wdt2[2*k+1], v.u2[1], acc2);
                }
                float alo, ahi; unpack2(acc2, alo, ahi);
                float dr = alo + ahi;
                float delta = (dr > 20.0f) ? dr : log1pf(__expf(dr));
                float xcv = xc_s[po*128 + dd3];
                float dBx = delta * xcv;
                ull dBx2 = pack2(dBx, dBx);
                ull B2[8], C2[8];
                #pragma unroll
                for (int k = 0; k < 4; k++) {
                    F4U2 v; v.f4 = db4[8+k];
                    B2[2*k] = v.u2[0]; B2[2*k+1] = v.u2[1];
                }
                #pragma unroll
                for (int k = 0; k < 4; k++) {
                    F4U2 v; v.f4 = db4[12+k];
                    C2[2*k] = v.u2[0]; C2[2*k+1] = v.u2[1];
                }
                size_t pos512 = ((size_t)(b*LL + (lvalid ? l : 0))) << 9;
                ull hv2[8];
                if (hmode == 0) {
                    #pragma unroll
                    for (int k = 0; k < 8; k++) hv2[k] = pack2(0.0f, 0.0f);
                } else {
                    #pragma unroll
                    for (int sg = 0; sg < 4; sg++) {
                        F4U2 v;
                        v.f4 = lvalid ? HS[pos512 + (sg<<7) + dd3]
                                      : make_float4(0.f,0.f,0.f,0.f);
                        hv2[2*sg] = v.u2[0]; hv2[2*sg+1] = v.u2[1];
                    }
                }
                ull y2 = pack2(0.0f, 0.0f);
                if (fastA) {
                    float E1 = __expf(-delta);
                    float Esq = E1*E1;
                    ull Echain = pack2(Esq, Esq);
                    ull da = pack2(E1, Esq);
                    #pragma unroll
                    for (int k = 0; k < 8; k++) {
                        ull tmp = mul2(dBx2, B2[k]);
                        ull hn  = fma2(da, hv2[k], tmp);
                        hv2[k] = hn;
                        y2 = fma2(hn, C2[k], y2);
                        if (k < 7) da = mul2(da, Echain);
                    }
                } else {
                    #pragma unroll
                    for (int k = 0; k < 8; k++) {
                        float na0 = __expf(__ldg(&A_log[dd3*16 + 2*k]));
                        float na1 = __expf(__ldg(&A_log[dd3*16 + 2*k + 1]));
                        ull da = pack2(__expf(-delta*na0), __expf(-delta*na1));
                        ull tmp = mul2(dBx2, B2[k]);
                        ull hn  = fma2(da, hv2[k], tmp);
                        hv2[k] = hn;
                        y2 = fma2(hn, C2[k], y2);
                    }
                }
                float ylo, yhi; unpack2(y2, ylo, yhi);
                float y = ylo + yhi;
                if (lvalid) {
                    if (hmode == 2) {
                        #pragma unroll
                        for (int sg = 0; sg < 4; sg++) {
                            F4U2 v; v.u2[0] = hv2[2*sg]; v.u2[1] = hv2[2*sg+1];
                            HD[pos512 + (dd3<<2) + sg] = v.f4;
                        }
                    } else {
                        #pragma unroll
                        for (int sg = 0; sg < 4; sg++) {
                            F4U2 v; v.u2[0] = hv2[2*sg]; v.u2[1] = hv2[2*sg+1];
                            HS[pos512 + (sg<<7) + dd3] = v.f4;
                        }
                    }
                }
                y += Dpv * xcv;
                float zv = z_s[po*128 + dd3];
                gS[po*128 + dd3] = y * (zv / (1.0f + __expf(-zv)));
            }
        }
        __syncthreads();

        // ---- phase 3d: out_proj + residual (4c x 2p tiles, f32x2, 4d unroll) ----
        {
            int jt = t & 15;
            int pt = t >> 4;
            if (pt < TT/2) {
                const int p0 = pt*2, p1 = p0 + 1;
                ull a0l = pack2(0,0), a0h = pack2(0,0);
                ull a1l = pack2(0,0), a1h = pack2(0,0);
                #pragma unroll 4
                for (int d4 = 0; d4 < 32; d4++) {
                    float4 ga4 = *(const float4*)(gS + p0*128 + d4*4);
                    float4 gb4 = *(const float4*)(gS + p1*128 + d4*4);
                    float ga[4] = {ga4.x, ga4.y, ga4.z, ga4.w};
                    float gb[4] = {gb4.x, gb4.y, gb4.z, gb4.w};
                    #pragma unroll
                    for (int e = 0; e < 4; e++) {
                        F4U2 w; w.f4 = *(const float4*)(outprojT + (d4*4+e)*64 + jt*4);
                        ull ga2 = pack2(ga[e], ga[e]);
                        ull gb2 = pack2(gb[e], gb[e]);
                        a0l = fma2(w.u2[0], ga2, a0l);
                        a0h = fma2(w.u2[1], ga2, a0h);
                        a1l = fma2(w.u2[0], gb2, a1l);
                        a1h = fma2(w.u2[1], gb2, a1h);
                    }
                }
                F4U2 o0; o0.u2[0] = a0l; o0.u2[1] = a0h;
                F4U2 o1; o1.u2[0] = a1l; o1.u2[1] = a1h;
                if (l0 + p0 < LL) {
                    float4 r0 = ((const float4*)(xn_r + p0*64))[jt];
                    o0.f4.x += r0.x; o0.f4.y += r0.y; o0.f4.z += r0.z; o0.f4.w += r0.w;
                    ((float4*)(outp + ((size_t)(b*LL + l0 + p0))*64))[jt] = o0.f4;
                }
                if (l0 + p1 < LL) {
                    float4 r1 = ((const float4*)(xn_r + p1*64))[jt];
                    o1.f4.x += r1.x; o1.f4.y += r1.y; o1.f4.z += r1.z; o1.f4.w += r1.w;
                    ((float4*)(outp + ((size_t)(b*LL + l0 + p1))*64))[jt] = o1.f4;
                }
            }
        }

        if (blk < 5) { grid_sync(GRID*ep); ep++; }
    }

    // ================= conv_out stage (pointwise in l: no grid sync needed) =======
    __syncthreads();
    {
        float* x_s = xn_s;     // [p][65] 3640 <= 3840
        float* wT3 = xcraw_s;  // [c][65]
        float* res = z_s;      // [o][57]
        const float* fin = buf1;   // block 5 wrote buf1
        for (int lin = t; lin < 64*64; lin += NTH)
            wT3[(lin & 63)*65 + (lin >> 6)] = w3[lin];
        for (int lin = t; lin < TT*64; lin += NTH) {
            int p = lin >> 6, c = lin & 63;
            int l = l0 + p;
            x_s[p*65 + c] = (l < LL) ? fin[(size_t)(b*LL + l)*64 + c] : 0.0f;
        }
        __syncthreads();
        int o = t & 63, pslot = t >> 6;
        float bv = b3[o];
        for (int p = pslot; p < TT; p += 8) {
            float acc = bv;
            #pragma unroll 8
            for (int c = 0; c < 64; c++)
                acc += wT3[c*65 + o] * x_s[p*65 + c];
            res[o*57 + p] = acc;
        }
        __syncthreads();
        for (int lin = t; lin < 64*TT; lin += NTH) {
            int oo = lin / TT, p = lin - oo*TT;
            int l = l0 + p;
            if (l < LL) out[(size_t)(b*64 + oo)*LL + l] = res[oo*57 + p];
        }
    }
}

// ---------------- launch ----------------
extern "C" void kernel_launch(void* const* d_in, const int* in_sizes, int n_in,
                              void* d_out, int out_size) {
    const float* rgb   = (const float*)d_in[0];
    const float* dte   = (const float*)d_in[1];
    const float* w1    = (const float*)d_in[2];
    const float* b1    = (const float*)d_in[3];
    const float* w2    = (const float*)d_in[4];
    const float* b2    = (const float*)d_in[5];
    const float* w3    = (const float*)d_in[6];
    const float* b3    = (const float*)d_in[7];
    const float* normw = (const float*)d_in[8];
    const float* inpw  = (const float*)d_in[9];
    const float* c1w   = (const float*)d_in[10];
    const float* c1b   = (const float*)d_in[11];
    const float* xpw   = (const float*)d_in[12];
    const float* dtw   = (const float*)d_in[13];
    const float* dtb   = (const float*)d_in[14];
    const float* alog  = (const float*)d_in[15];
    const float* DpP   = (const float*)d_in[16];
    const float* opw   = (const float*)d_in[17];

    float* out = (float*)d_out;
    const int convN = BB*CC*LL;                  // 524288
    const long long hN = (long long)BB*LL*DI*SS; // 16777216
    float* hfinal;
    if (out_size >= convN + hN) {
        hfinal = out + convN;
    } else {
        void* p; cudaGetSymbolAddress(&p, g_hfallback); hfinal = (float*)p;
    }

    cudaFuncSetAttribute(fused_kernel,
                         cudaFuncAttributeMaxDynamicSharedMemorySize, SMEM_BYTES);

    reset_kernel<<<1, 1>>>();
    fused_kernel<<<GRID, NTH, SMEM_BYTES>>>(
        rgb, dte, w1, b1, w2, b2, w3, b3,
        normw, inpw, c1w, c1b, xpw, dtw, dtb, alog, DpP, opw,
        out, hfinal);
    (void)in_sizes; (void)n_in;
}